// round 4
// baseline (speedup 1.0000x reference)
#include <cuda_runtime.h>
#include <cstdint>

// ---------------------------------------------------------------------------
// Attention_12970801234467 — 3xTF32 tensor-core version
//   q = Q@W+b ; k = K@W+b ; v = V@W+b   (same W for all three, per reference)
//   logits = q k^T / 32 ; w = softmax(logits) ; out = w v
// Shapes: B=8, S=2048, D=1024.  All GEMMs via mma.sync m16n8k8 tf32 with
// hi/lo error compensation (3 MMAs per tile-pair) -> fp32-class accuracy.
// ---------------------------------------------------------------------------

#define BATCH 8
#define SEQ   2048
#define DIM   1024
#define NROWS (BATCH * SEQ)        // 16384

#define BM 128
#define BN 128
#define BK 16
#define SMK (BK)
#define SMLD 136                   // padded plane stride: conflict-free frag LDS

__device__ float g_q[(size_t)NROWS * DIM];
__device__ float g_k[(size_t)NROWS * DIM];
__device__ float g_v[(size_t)NROWS * DIM];
__device__ float g_logits[(size_t)BATCH * SEQ * SEQ];

// ---- tf32 split: x = hi + lo, both tf32-representable ----------------------
__device__ __forceinline__ void split_tf32(float x, uint32_t& hi, uint32_t& lo) {
    uint32_t h;
    asm("cvt.rna.tf32.f32 %0, %1;" : "=r"(h) : "f"(x));
    float r = x - __uint_as_float(h);   // exact (hi has zeroed low mantissa)
    uint32_t l;
    asm("cvt.rna.tf32.f32 %0, %1;" : "=r"(l) : "f"(r));
    hi = h; lo = l;
}

__device__ __forceinline__ void mma1688(float c[4],
                                        uint32_t a0, uint32_t a1, uint32_t a2, uint32_t a3,
                                        uint32_t b0, uint32_t b1) {
    asm volatile(
        "mma.sync.aligned.m16n8k8.row.col.f32.tf32.tf32.f32 "
        "{%0,%1,%2,%3}, {%4,%5,%6,%7}, {%8,%9}, {%0,%1,%2,%3};\n"
        : "+f"(c[0]), "+f"(c[1]), "+f"(c[2]), "+f"(c[3])
        : "r"(a0), "r"(a1), "r"(a2), "r"(a3), "r"(b0), "r"(b1));
}

// ---------------------------------------------------------------------------
// C = alpha * A * op(B) (+ bias).  A:[M,K] rm.  TRANSB? B:[N,K] rm : B:[K,N] rm.
// Batched over blockIdx.z with element strides. Dims multiples of tiles.
// 256 threads = 8 warps (2 m-warps x 4 n-warps), warp tile 64x32.
// ---------------------------------------------------------------------------
template <bool TRANSB, bool BIAS>
__global__ __launch_bounds__(256)
void gemm_tf32(const float* __restrict__ A, const float* __restrict__ Bm,
               const float* __restrict__ bias, float* __restrict__ C,
               int M, int N, int K,
               long long sA, long long sB, long long sC, float alpha)
{
    __shared__ float As[2][SMK][SMLD];   // k-major planes: As[kk][m]
    __shared__ float Bs[2][SMK][SMLD];   // Bs[kk][n]

    const int tid  = threadIdx.x;
    const int warp = tid >> 5;
    const int lane = tid & 31;
    const int gid  = lane >> 2;    // 0..7
    const int tig  = lane & 3;     // 0..3
    const int wm   = warp & 1;     // 0..1  (m)
    const int wn   = warp >> 1;    // 0..3  (n)

    const long long z = blockIdx.z;
    A  += z * sA;
    Bm += z * sB;
    C  += z * sC;

    const int mbase = blockIdx.y * BM;
    const int nbase = blockIdx.x * BN;

    float acc[4][4][4];
#pragma unroll
    for (int i = 0; i < 4; i++)
#pragma unroll
        for (int j = 0; j < 4; j++)
#pragma unroll
            for (int r = 0; r < 4; r++) acc[i][j][r] = 0.0f;

    float4 pa[2], pb[2];

    // --- global loaders (stage into registers) ---
    auto ldg_tiles = [&](int kt) {
#pragma unroll
        for (int i = 0; i < 2; i++) {
            int idx = tid + i * 256;            // 0..511
            {   // A: 128 rows x 16k -> float4 along k
                int r  = idx & 127;
                int kq = idx >> 7;              // 0..3
                pa[i] = *(const float4*)(A + (long long)(mbase + r) * K + kt + kq * 4);
            }
            if (TRANSB) {                        // B [N,K]: float4 along k
                int r  = idx & 127;
                int kq = idx >> 7;
                pb[i] = *(const float4*)(Bm + (long long)(nbase + r) * K + kt + kq * 4);
            } else {                             // B [K,N]: float4 along n
                int kk = idx >> 5;              // 0..15
                int n4 = idx & 31;
                pb[i] = *(const float4*)(Bm + (long long)(kt + kk) * N + nbase + n4 * 4);
            }
        }
    };

    auto sts_tiles = [&](int buf) {
#pragma unroll
        for (int i = 0; i < 2; i++) {
            int idx = tid + i * 256;
            {   // A scatter: As[kq*4+j][row]
                int r  = idx & 127;
                int kq = idx >> 7;
                As[buf][kq * 4 + 0][r] = pa[i].x;
                As[buf][kq * 4 + 1][r] = pa[i].y;
                As[buf][kq * 4 + 2][r] = pa[i].z;
                As[buf][kq * 4 + 3][r] = pa[i].w;
            }
            if (TRANSB) {
                int r  = idx & 127;
                int kq = idx >> 7;
                Bs[buf][kq * 4 + 0][r] = pb[i].x;
                Bs[buf][kq * 4 + 1][r] = pb[i].y;
                Bs[buf][kq * 4 + 2][r] = pb[i].z;
                Bs[buf][kq * 4 + 3][r] = pb[i].w;
            } else {
                int kk = idx >> 5;
                int n4 = idx & 31;
                *(float4*)&Bs[buf][kk][n4 * 4] = pb[i];
            }
        }
    };

    const int T = K / BK;
    ldg_tiles(0);
    sts_tiles(0);
    __syncthreads();

    for (int t = 0; t < T; t++) {
        const int buf = t & 1;
        if (t + 1 < T) ldg_tiles((t + 1) * BK);

        // --- compute on smem[buf]: two k8 sub-steps ---
#pragma unroll
        for (int ks = 0; ks < 2; ks++) {
            const int kb = ks * 8;
            uint32_t ah[4][4], al[4][4];
#pragma unroll
            for (int ma = 0; ma < 4; ma++) {
                const int m0 = wm * 64 + ma * 16 + gid;
                float x0 = As[buf][kb + tig][m0];
                float x1 = As[buf][kb + tig][m0 + 8];
                float x2 = As[buf][kb + tig + 4][m0];
                float x3 = As[buf][kb + tig + 4][m0 + 8];
                split_tf32(x0, ah[ma][0], al[ma][0]);
                split_tf32(x1, ah[ma][1], al[ma][1]);
                split_tf32(x2, ah[ma][2], al[ma][2]);
                split_tf32(x3, ah[ma][3], al[ma][3]);
            }
            uint32_t bh[4][2], bl[4][2];
#pragma unroll
            for (int na = 0; na < 4; na++) {
                const int n0 = wn * 32 + na * 8 + gid;
                float y0 = Bs[buf][kb + tig][n0];
                float y1 = Bs[buf][kb + tig + 4][n0];
                split_tf32(y0, bh[na][0], bl[na][0]);
                split_tf32(y1, bh[na][1], bl[na][1]);
            }
#pragma unroll
            for (int ma = 0; ma < 4; ma++)
#pragma unroll
                for (int na = 0; na < 4; na++) {
                    // hi*hi + hi*lo + lo*hi  (3xTF32 compensation)
                    mma1688(acc[ma][na], ah[ma][0], ah[ma][1], ah[ma][2], ah[ma][3],
                            bh[na][0], bh[na][1]);
                    mma1688(acc[ma][na], ah[ma][0], ah[ma][1], ah[ma][2], ah[ma][3],
                            bl[na][0], bl[na][1]);
                    mma1688(acc[ma][na], al[ma][0], al[ma][1], al[ma][2], al[ma][3],
                            bh[na][0], bh[na][1]);
                }
        }

        if (t + 1 < T) {
            __syncthreads();             // prior buffer's readers done
            sts_tiles((t + 1) & 1);
            __syncthreads();             // new tile visible
        }
    }

    // --- epilogue: c0,c1 at (row, col..col+1), c2,c3 at (row+8, ...) ---
#pragma unroll
    for (int ma = 0; ma < 4; ma++) {
        const int row0 = mbase + wm * 64 + ma * 16 + gid;
#pragma unroll
        for (int na = 0; na < 4; na++) {
            const int col = nbase + wn * 32 + na * 8 + tig * 2;
            float2 o0, o1;
            o0.x = alpha * acc[ma][na][0];
            o0.y = alpha * acc[ma][na][1];
            o1.x = alpha * acc[ma][na][2];
            o1.y = alpha * acc[ma][na][3];
            if (BIAS) {
                o0.x += bias[col];     o0.y += bias[col + 1];
                o1.x += bias[col];     o1.y += bias[col + 1];
            }
            *(float2*)(C + (long long)row0 * N + col)       = o0;
            *(float2*)(C + (long long)(row0 + 8) * N + col) = o1;
        }
    }
}

// ---------------------------------------------------------------------------
// Row softmax over S=2048, in place. One 256-thread block per row.
// ---------------------------------------------------------------------------
__global__ __launch_bounds__(256)
void softmax2048(float* __restrict__ logits)
{
    const long long row = blockIdx.x;
    float* p = logits + row * (long long)SEQ;
    const int tid = threadIdx.x;

    __shared__ float red[8];
    __shared__ float bcast;

    float v[8];
    float m = -1e30f;
#pragma unroll
    for (int i = 0; i < 8; i++) {
        v[i] = p[tid + i * 256];
        m = fmaxf(m, v[i]);
    }
#pragma unroll
    for (int o = 16; o > 0; o >>= 1) m = fmaxf(m, __shfl_xor_sync(0xffffffffu, m, o));
    if ((tid & 31) == 0) red[tid >> 5] = m;
    __syncthreads();
    if (tid == 0) {
        float t = red[0];
#pragma unroll
        for (int i = 1; i < 8; i++) t = fmaxf(t, red[i]);
        bcast = t;
    }
    __syncthreads();
    const float rmax = bcast;

    float s = 0.0f;
#pragma unroll
    for (int i = 0; i < 8; i++) {
        v[i] = expf(v[i] - rmax);
        s += v[i];
    }
#pragma unroll
    for (int o = 16; o > 0; o >>= 1) s += __shfl_xor_sync(0xffffffffu, s, o);
    if ((tid & 31) == 0) red[tid >> 5] = s;
    __syncthreads();
    if (tid == 0) {
        float t = 0.0f;
#pragma unroll
        for (int i = 0; i < 8; i++) t += red[i];
        bcast = 1.0f / t;
    }
    __syncthreads();
    const float inv = bcast;

#pragma unroll
    for (int i = 0; i < 8; i++) p[tid + i * 256] = v[i] * inv;
}

// ---------------------------------------------------------------------------
extern "C" void kernel_launch(void* const* d_in, const int* in_sizes, int n_in,
                              void* d_out, int out_size)
{
    const float* query = (const float*)d_in[0];
    const float* key   = (const float*)d_in[1];
    const float* value = (const float*)d_in[2];
    const float* Wq    = (const float*)d_in[3];
    const float* bq    = (const float*)d_in[4];
    float* out = (float*)d_out;

    float *q, *k, *v, *lg;
    cudaGetSymbolAddress((void**)&q,  g_q);
    cudaGetSymbolAddress((void**)&k,  g_k);
    cudaGetSymbolAddress((void**)&v,  g_v);
    cudaGetSymbolAddress((void**)&lg, g_logits);

    const dim3 blk(256);

    // Stage 1: projections  Y = X @ W + b   (M=16384, N=1024, K=1024)
    {
        dim3 g(DIM / BN, NROWS / BM, 1);
        gemm_tf32<false, true><<<g, blk>>>(query, Wq, bq, q, NROWS, DIM, DIM, 0, 0, 0, 1.0f);
        gemm_tf32<false, true><<<g, blk>>>(key,   Wq, bq, k, NROWS, DIM, DIM, 0, 0, 0, 1.0f);
        gemm_tf32<false, true><<<g, blk>>>(value, Wq, bq, v, NROWS, DIM, DIM, 0, 0, 0, 1.0f);
    }

    // Stage 2: logits[b] = q[b] @ k[b]^T / 32   (M=N=2048, K=1024, batched)
    {
        dim3 g(SEQ / BN, SEQ / BM, BATCH);
        gemm_tf32<true, false><<<g, blk>>>(q, k, nullptr, lg,
                                           SEQ, SEQ, DIM,
                                           (long long)SEQ * DIM, (long long)SEQ * DIM,
                                           (long long)SEQ * SEQ, 0.03125f);
    }

    // Stage 3: softmax rows (B*S rows of length S)
    softmax2048<<<NROWS, 256>>>(lg);

    // Stage 4: out[b] = w[b] @ v[b]   (M=2048, N=1024, K=2048, batched)
    {
        dim3 g(DIM / BN, SEQ / BM, BATCH);
        gemm_tf32<false, false><<<g, blk>>>(lg, v, nullptr, out,
                                            SEQ, DIM, SEQ,
                                            (long long)SEQ * SEQ, (long long)SEQ * DIM,
                                            (long long)SEQ * DIM, 1.0f);
    }
}